// round 1
// baseline (speedup 1.0000x reference)
#include <cuda_runtime.h>
#include <float.h>

#define Bv 64
#define Nv 1024
#define Dv 128
#define Kv 6

// Scratch (device globals: no allocation allowed)
__device__ float g_ABC[Kv * Dv * 3];        // [k][d][{A,B,C}]
__device__ float g_partial[Bv * 4 * Dv];    // per (b, chunk) partial row-sums

// ---------------------------------------------------------------------------
// Kernel A: fold W2d/b2d through Wnb:
//   A_k[d] = sum_e W2d[e,0]*Wnb[d, k*D+e]
//   B_k[d] = sum_e W2d[e,1]*Wnb[d, k*D+e]
//   C_k[d] = sum_e b2d[e]  *Wnb[d, k*D+e]
// ---------------------------------------------------------------------------
__global__ void abc_kernel(const float* __restrict__ W2d,
                           const float* __restrict__ b2d,
                           const float* __restrict__ Wnb)
{
    int k = blockIdx.x, d = threadIdx.x;
    const float* wrow = Wnb + (size_t)d * (Kv * Dv) + k * Dv;
    float A = 0.f, B = 0.f, C = 0.f;
#pragma unroll 8
    for (int e = 0; e < Dv; e++) {
        float w = wrow[e];
        A = fmaf(w, W2d[e * 2 + 0], A);
        B = fmaf(w, W2d[e * 2 + 1], B);
        C = fmaf(w, b2d[e], C);
    }
    int base = (k * Dv + d) * 3;
    g_ABC[base + 0] = A;
    g_ABC[base + 1] = B;
    g_ABC[base + 2] = C;
}

// ---------------------------------------------------------------------------
// Kernel B: per (batch b, 256-row chunk):
//   phase 1: stage loc[b] and loc[0] in smem, stage folded weights
//   phase 2: per-thread scan of 1024 candidates, register top-6 by squared
//            distance (strict < == top_k's lower-index tie-break)
//   phase 3: h[b, 1+row, d] = leaky( base[d] + x*w0 + y*w1 + dl*w2
//                                    + sum_k (nx_k*A_k[d] + ny_k*B_k[d]) )
//            with deterministic partial-sum accumulation for the mean
// ---------------------------------------------------------------------------
__global__ __launch_bounds__(256) void main_kernel(
    const float* __restrict__ loc, const float* __restrict__ deadline,
    const float* __restrict__ W3d, const float* __restrict__ b3d,
    const float* __restrict__ bnb, float* __restrict__ h_out)
{
    __shared__ float2 sloc[Nv];       // batch-b coords (distances)
    __shared__ float2 sloc0[Nv];      // batch-0 coords (feature gather)
    __shared__ float4 srow[256];      // (x, y, deadline, -) per row
    __shared__ float2 snb[256 * Kv];  // neighbor batch-0 coords per row
    __shared__ float4 sW3[Dv];        // (w0, w1, w2, base) per d
    __shared__ float2 sAB[Kv * Dv];   // (A_k[d], B_k[d])
    __shared__ float  sred[Dv];

    const int b = blockIdx.y, chunk = blockIdx.x, t = threadIdx.x;

    const float2* locb = (const float2*)(loc + (size_t)b * Nv * 2);
    const float2* l0   = (const float2*)loc;
    for (int i = t; i < Nv; i += 256) { sloc[i] = locb[i]; sloc0[i] = l0[i]; }

    if (t < Dv) {
        float sumC = 0.f;
#pragma unroll
        for (int k = 0; k < Kv; k++) {
            int base = (k * Dv + t) * 3;
            sAB[k * Dv + t] = make_float2(g_ABC[base], g_ABC[base + 1]);
            sumC += g_ABC[base + 2];
        }
        sW3[t] = make_float4(W3d[t * 3 + 0], W3d[t * 3 + 1], W3d[t * 3 + 2],
                             b3d[t] + bnb[t] + sumC);
    }
    __syncthreads();

    // ---- phase 2: top-6 nearest (squared distance, reference rounding) ----
    const int row = chunk * 256 + t;
    const float mx = sloc[row].x, my = sloc[row].y;
    float d0 = FLT_MAX, d1 = FLT_MAX, d2 = FLT_MAX,
          d3 = FLT_MAX, d4 = FLT_MAX, d5 = FLT_MAX;
    int i0 = 0, i1 = 0, i2 = 0, i3 = 0, i4 = 0, i5 = 0;

#pragma unroll 4
    for (int j = 0; j < Nv; j++) {
        float2 p = sloc[j];                       // broadcast LDS.64
        float dx = p.x - mx, dy = p.y - my;
        float dd = __fadd_rn(__fmul_rn(dx, dx), __fmul_rn(dy, dy));
        if (dd < d5) {                            // rare path (~42/1024 rows)
            if (dd < d2) {
                if (dd < d1) {
                    if (dd < d0) {
                        d5=d4;i5=i4; d4=d3;i4=i3; d3=d2;i3=i2;
                        d2=d1;i2=i1; d1=d0;i1=i0; d0=dd;i0=j;
                    } else {
                        d5=d4;i5=i4; d4=d3;i4=i3; d3=d2;i3=i2;
                        d2=d1;i2=i1; d1=dd;i1=j;
                    }
                } else {
                    d5=d4;i5=i4; d4=d3;i4=i3; d3=d2;i3=i2; d2=dd;i2=j;
                }
            } else {
                if (dd < d4) {
                    if (dd < d3) { d5=d4;i5=i4; d4=d3;i4=i3; d3=dd;i3=j; }
                    else         { d5=d4;i5=i4; d4=dd;i4=j; }
                } else           { d5=dd;i5=j; }
            }
        }
    }
    snb[t*Kv+0] = sloc0[i0]; snb[t*Kv+1] = sloc0[i1]; snb[t*Kv+2] = sloc0[i2];
    snb[t*Kv+3] = sloc0[i3]; snb[t*Kv+4] = sloc0[i4]; snb[t*Kv+5] = sloc0[i5];
    srow[t] = make_float4(mx, my, deadline[(size_t)b * Nv + row], 0.f);
    __syncthreads();

    // ---- phase 3: features, fixed d per thread, rows split in halves ----
    const int d    = t & (Dv - 1);
    const int half = t >> 7;
    const float4 w = sW3[d];
    float A[Kv], Bc[Kv];
#pragma unroll
    for (int k = 0; k < Kv; k++) { float2 ab = sAB[k * Dv + d]; A[k] = ab.x; Bc[k] = ab.y; }

    float acc = 0.f;
    float* outp = h_out + ((size_t)b * 1025 + 1 + chunk * 256 + half * Dv) * Dv + d;
#pragma unroll 2
    for (int r = 0; r < Dv; r++) {
        int rr = half * Dv + r;
        float4 rd = srow[rr];                     // broadcast LDS.128
        float v = w.w;
        v = fmaf(rd.x, w.x, v);
        v = fmaf(rd.y, w.y, v);
        v = fmaf(rd.z, w.z, v);
#pragma unroll
        for (int k = 0; k < Kv; k++) {
            float2 nb = snb[rr * Kv + k];         // broadcast LDS.64
            v = fmaf(nb.x, A[k], v);
            v = fmaf(nb.y, Bc[k], v);
        }
        v = fmaxf(v, 0.01f * v);                  // leaky_relu(0.01)
        outp[(size_t)r * Dv] = v;                 // coalesced over d
        acc += v;
    }
    if (half == 1) sred[d] = acc;
    __syncthreads();
    if (half == 0) g_partial[(b * 4 + chunk) * Dv + d] = acc + sred[d];
}

// ---------------------------------------------------------------------------
// Kernel C: depot row + mean over axis 1 (1025 rows), deterministic order
// ---------------------------------------------------------------------------
__global__ void tail_kernel(const float* __restrict__ depot,
                            const float* __restrict__ Wdep,
                            const float* __restrict__ bdep,
                            float* __restrict__ out)
{
    int b = blockIdx.x, d = threadIdx.x;
    float v = bdep[d];
    v = fmaf(depot[b * 2 + 0], Wdep[d * 2 + 0], v);
    v = fmaf(depot[b * 2 + 1], Wdep[d * 2 + 1], v);
    v = fmaxf(v, 0.01f * v);
    out[(size_t)b * 1025 * Dv + d] = v;           // h[b, 0, d]
    float s = v;
#pragma unroll
    for (int c = 0; c < 4; c++) s += g_partial[(b * 4 + c) * Dv + d];
    out[(size_t)Bv * 1025 * Dv + b * Dv + d] = s / 1025.0f;
}

// ---------------------------------------------------------------------------
extern "C" void kernel_launch(void* const* d_in, const int* in_sizes, int n_in,
                              void* d_out, int out_size)
{
    const float* loc      = (const float*)d_in[0];
    const float* deadline = (const float*)d_in[1];
    const float* depot    = (const float*)d_in[2];
    const float* W3d      = (const float*)d_in[3];
    const float* b3d      = (const float*)d_in[4];
    const float* W2d      = (const float*)d_in[5];
    const float* b2d      = (const float*)d_in[6];
    const float* Wnb      = (const float*)d_in[7];
    const float* bnb      = (const float*)d_in[8];
    const float* Wdep     = (const float*)d_in[9];
    const float* bdep     = (const float*)d_in[10];
    float* out = (float*)d_out;

    abc_kernel<<<Kv, Dv>>>(W2d, b2d, Wnb);
    dim3 grid(4, Bv);
    main_kernel<<<grid, 256>>>(loc, deadline, W3d, b3d, bnb, out);
    tail_kernel<<<Bv, Dv>>>(depot, Wdep, bdep, out);
}

// round 2
// speedup vs baseline: 1.1772x; 1.1772x over previous
#include <cuda_runtime.h>
#include <float.h>

#define Bv 64
#define Nv 1024
#define Dv 128
#define Kv 6
#define CHUNKS 8
#define ROWS 128   // rows per block

__device__ float g_ABC[Kv * Dv * 3];            // [k][d][{A,B,C}]
__device__ float g_partial[Bv * CHUNKS * Dv];   // per (b, chunk) partial row-sums

// ---- packed f32x2 helpers (per-half rn rounding == separate FADD/FMUL) ----
__device__ __forceinline__ unsigned long long f2add(unsigned long long a, unsigned long long b) {
    unsigned long long r; asm("add.rn.f32x2 %0,%1,%2;" : "=l"(r) : "l"(a), "l"(b)); return r;
}
__device__ __forceinline__ unsigned long long f2mul(unsigned long long a, unsigned long long b) {
    unsigned long long r; asm("mul.rn.f32x2 %0,%1,%2;" : "=l"(r) : "l"(a), "l"(b)); return r;
}
__device__ __forceinline__ unsigned long long f2pack(float lo, float hi) {
    unsigned long long r; asm("mov.b64 %0,{%1,%2};" : "=l"(r) : "f"(lo), "f"(hi)); return r;
}
__device__ __forceinline__ void f2unpack(unsigned long long v, float& lo, float& hi) {
    asm("mov.b64 {%0,%1},%2;" : "=f"(lo), "=f"(hi) : "l"(v));
}

// ---------------------------------------------------------------------------
// Kernel A: fold W2d/b2d through Wnb. One warp per (k,d). 768 warps.
// ---------------------------------------------------------------------------
__global__ __launch_bounds__(256) void abc_kernel(
    const float* __restrict__ W2d, const float* __restrict__ b2d,
    const float* __restrict__ Wnb)
{
    int wid  = blockIdx.x * 8 + (threadIdx.x >> 5);   // 0..767
    int k    = wid >> 7, d = wid & (Dv - 1);
    int lane = threadIdx.x & 31;

    const float4* w4 = (const float4*)(Wnb + (size_t)d * (Kv * Dv) + k * Dv);
    float4 v  = w4[lane];                              // e = lane*4 .. +3
    const float4* w2 = (const float4*)W2d;             // pairs (W2d[e,0],W2d[e,1])
    float4 p0 = w2[lane * 2], p1 = w2[lane * 2 + 1];
    float4 bb = ((const float4*)b2d)[lane];

    float A = fmaf(v.x, p0.x, fmaf(v.y, p0.z, fmaf(v.z, p1.x, v.w * p1.z)));
    float B = fmaf(v.x, p0.y, fmaf(v.y, p0.w, fmaf(v.z, p1.y, v.w * p1.w)));
    float C = fmaf(v.x, bb.x, fmaf(v.y, bb.y, fmaf(v.z, bb.z, v.w * bb.w)));
#pragma unroll
    for (int s = 16; s > 0; s >>= 1) {
        A += __shfl_xor_sync(0xffffffffu, A, s);
        B += __shfl_xor_sync(0xffffffffu, B, s);
        C += __shfl_xor_sync(0xffffffffu, C, s);
    }
    if (lane == 0) {
        int base = (k * Dv + d) * 3;
        g_ABC[base + 0] = A; g_ABC[base + 1] = B; g_ABC[base + 2] = C;
    }
}

// ---------------------------------------------------------------------------
// Kernel B: per (batch b, 128-row chunk), 256 threads.
//   phase 2: thread t scans half (t>>7) of 1024 candidates for row (t&127)
//            with packed f32x2 math; halves merged (first-half wins ties ==
//            top_k lower-index tie-break).
//   phase 3: thread t = (d, row-half); fused affine features + leaky_relu.
// ---------------------------------------------------------------------------
__global__ __launch_bounds__(256) void main_kernel(
    const float* __restrict__ loc, const float* __restrict__ deadline,
    const float* __restrict__ W3d, const float* __restrict__ b3d,
    const float* __restrict__ bnb, float* __restrict__ h_out)
{
    __shared__ __align__(16) float sloc_raw[Nv * 2];   // batch-b coords
    __shared__ __align__(16) float sloc0_raw[Nv * 2];  // batch-0 coords
    __shared__ float4 srow[ROWS];                      // (x, y, deadline, -)
    __shared__ float2 snb[ROWS * Kv];                  // neighbor batch-0 coords
    __shared__ float4 sW3[Dv];                         // (w0,w1,w2, base)
    __shared__ float2 sAB[Kv * Dv];                    // (A_k[d], B_k[d])
    __shared__ float  pd[ROWS * Kv];                   // partner half top-6 dists
    __shared__ int    pi[ROWS * Kv];                   // partner half top-6 idx
    __shared__ float  sred[Dv];

    const int b = blockIdx.y, chunk = blockIdx.x, t = threadIdx.x;

    {   // phase 1: stage coords (float4 = 2 points per load)
        const float4* lb4 = (const float4*)(loc + (size_t)b * Nv * 2);
        const float4* l04 = (const float4*)loc;
        ((float4*)sloc_raw)[t]  = lb4[t];
        ((float4*)sloc0_raw)[t] = l04[t];
        ((float4*)sloc_raw)[t + 256]  = lb4[t + 256];
        ((float4*)sloc0_raw)[t + 256] = l04[t + 256];
    }
    if (t < Dv) {
        float sumC = 0.f;
#pragma unroll
        for (int k = 0; k < Kv; k++) {
            int base = (k * Dv + t) * 3;
            sAB[k * Dv + t] = make_float2(g_ABC[base], g_ABC[base + 1]);
            sumC += g_ABC[base + 2];
        }
        sW3[t] = make_float4(W3d[t * 3 + 0], W3d[t * 3 + 1], W3d[t * 3 + 2],
                             b3d[t] + bnb[t] + sumC);
    }
    __syncthreads();

    // ---- phase 2: half-scan of 512 candidates, register top-6 ----
    const int  rloc = t & (ROWS - 1);
    const int  half = t >> 7;
    const int  grow = chunk * ROWS + rloc;
    const float2* slocv = (const float2*)sloc_raw;
    const float2 m = slocv[grow];
    const unsigned long long negm = f2pack(-m.x, -m.y);

    float d0 = FLT_MAX, d1 = FLT_MAX, d2 = FLT_MAX,
          d3 = FLT_MAX, d4 = FLT_MAX, d5 = FLT_MAX;
    int i0 = 0, i1 = 0, i2 = 0, i3 = 0, i4 = 0, i5 = 0;

#define INSERT(dd, jj)                                                        \
    if (dd < d5) {                                                            \
        if (dd < d2) {                                                        \
            if (dd < d1) {                                                    \
                if (dd < d0) { d5=d4;i5=i4; d4=d3;i4=i3; d3=d2;i3=i2;         \
                               d2=d1;i2=i1; d1=d0;i1=i0; d0=dd;i0=jj; }       \
                else         { d5=d4;i5=i4; d4=d3;i4=i3; d3=d2;i3=i2;         \
                               d2=d1;i2=i1; d1=dd;i1=jj; }                    \
            } else           { d5=d4;i5=i4; d4=d3;i4=i3; d3=d2;i3=i2;         \
                               d2=dd;i2=jj; }                                 \
        } else {                                                              \
            if (dd < d4) {                                                    \
                if (dd < d3) { d5=d4;i5=i4; d4=d3;i4=i3; d3=dd;i3=jj; }       \
                else         { d5=d4;i5=i4; d4=dd;i4=jj; }                    \
            } else           { d5=dd;i5=jj; }                                 \
        }                                                                     \
    }

    {
        const ulonglong2* sl2 = (const ulonglong2*)sloc_raw;  // 2 cands / 16B
        const int jj0 = half * 256;
#pragma unroll 4
        for (int jj = jj0; jj < jj0 + 256; jj++) {
            ulonglong2 q = sl2[jj];                    // broadcast LDS.128
            unsigned long long da = f2add(q.x, negm);
            unsigned long long db = f2add(q.y, negm);
            unsigned long long sa = f2mul(da, da);
            unsigned long long sb = f2mul(db, db);
            float alo, ahi, blo, bhi;
            f2unpack(sa, alo, ahi); f2unpack(sb, blo, bhi);
            float ddA = __fadd_rn(alo, ahi);
            float ddB = __fadd_rn(blo, bhi);
            INSERT(ddA, 2 * jj);
            INSERT(ddB, 2 * jj + 1);
        }
    }
#undef INSERT

    if (half == 1) {   // publish second-half list
        pd[rloc*Kv+0]=d0; pd[rloc*Kv+1]=d1; pd[rloc*Kv+2]=d2;
        pd[rloc*Kv+3]=d3; pd[rloc*Kv+4]=d4; pd[rloc*Kv+5]=d5;
        pi[rloc*Kv+0]=i0; pi[rloc*Kv+1]=i1; pi[rloc*Kv+2]=i2;
        pi[rloc*Kv+3]=i3; pi[rloc*Kv+4]=i4; pi[rloc*Kv+5]=i5;
    }
    __syncthreads();

    if (half == 0) {   // merge: two-pointer, first half wins ties (lower idx)
        float b0=pd[rloc*Kv+0], b1=pd[rloc*Kv+1], b2=pd[rloc*Kv+2],
              b3=pd[rloc*Kv+3], b4=pd[rloc*Kv+4], b5=pd[rloc*Kv+5];
        int   y0=pi[rloc*Kv+0], y1=pi[rloc*Kv+1], y2=pi[rloc*Kv+2],
              y3=pi[rloc*Kv+3], y4=pi[rloc*Kv+4], y5=pi[rloc*Kv+5];
        const float2* sl0 = (const float2*)sloc0_raw;
#pragma unroll
        for (int s = 0; s < Kv; s++) {
            bool ta = (d0 <= b0);
            int sel = ta ? i0 : y0;
            snb[rloc * Kv + s] = sl0[sel];
            if (ta) { d0=d1; d1=d2; d2=d3; d3=d4; d4=d5; d5=FLT_MAX;
                      i0=i1; i1=i2; i2=i3; i3=i4; i4=i5; }
            else    { b0=b1; b1=b2; b2=b3; b3=b4; b4=b5; b5=FLT_MAX;
                      y0=y1; y1=y2; y2=y3; y3=y4; y4=y5; }
        }
        srow[rloc] = make_float4(m.x, m.y, deadline[(size_t)b * Nv + grow], 0.f);
    }
    __syncthreads();

    // ---- phase 3: features; thread t = (d = t&127, row-half = t>>7) ----
    const int d    = t & (Dv - 1);
    const int rh   = t >> 7;               // 64 rows each
    const float4 w = sW3[d];
    float A[Kv], Bc[Kv];
#pragma unroll
    for (int k = 0; k < Kv; k++) { float2 ab = sAB[k * Dv + d]; A[k] = ab.x; Bc[k] = ab.y; }

    float acc = 0.f;
    float* outp = h_out + ((size_t)b * 1025 + 1 + chunk * ROWS + rh * 64) * Dv + d;
#pragma unroll 2
    for (int r = 0; r < 64; r++) {
        int rr = rh * 64 + r;
        float4 rd = srow[rr];                      // broadcast LDS.128
        float v = w.w;
        v = fmaf(rd.x, w.x, v);
        v = fmaf(rd.y, w.y, v);
        v = fmaf(rd.z, w.z, v);
#pragma unroll
        for (int k = 0; k < Kv; k++) {
            float2 nb = snb[rr * Kv + k];          // broadcast LDS.64
            v = fmaf(nb.x, A[k], v);
            v = fmaf(nb.y, Bc[k], v);
        }
        v = fmaxf(v, 0.01f * v);                   // leaky_relu(0.01)
        outp[(size_t)r * Dv] = v;                  // coalesced over d
        acc += v;
    }
    if (rh == 1) sred[d] = acc;
    __syncthreads();
    if (rh == 0) g_partial[((size_t)b * CHUNKS + chunk) * Dv + d] = acc + sred[d];
}

// ---------------------------------------------------------------------------
// Kernel C: depot row + mean over axis 1 (1025 rows)
// ---------------------------------------------------------------------------
__global__ void tail_kernel(const float* __restrict__ depot,
                            const float* __restrict__ Wdep,
                            const float* __restrict__ bdep,
                            float* __restrict__ out)
{
    int b = blockIdx.x, d = threadIdx.x;
    float v = bdep[d];
    v = fmaf(depot[b * 2 + 0], Wdep[d * 2 + 0], v);
    v = fmaf(depot[b * 2 + 1], Wdep[d * 2 + 1], v);
    v = fmaxf(v, 0.01f * v);
    out[(size_t)b * 1025 * Dv + d] = v;            // h[b, 0, d]
    float s = v;
#pragma unroll
    for (int c = 0; c < CHUNKS; c++) s += g_partial[((size_t)b * CHUNKS + c) * Dv + d];
    out[(size_t)Bv * 1025 * Dv + b * Dv + d] = s / 1025.0f;
}

// ---------------------------------------------------------------------------
extern "C" void kernel_launch(void* const* d_in, const int* in_sizes, int n_in,
                              void* d_out, int out_size)
{
    const float* loc      = (const float*)d_in[0];
    const float* deadline = (const float*)d_in[1];
    const float* depot    = (const float*)d_in[2];
    const float* W3d      = (const float*)d_in[3];
    const float* b3d      = (const float*)d_in[4];
    const float* W2d      = (const float*)d_in[5];
    const float* b2d      = (const float*)d_in[6];
    const float* Wnb      = (const float*)d_in[7];
    const float* bnb      = (const float*)d_in[8];
    const float* Wdep     = (const float*)d_in[9];
    const float* bdep     = (const float*)d_in[10];
    float* out = (float*)d_out;

    abc_kernel<<<96, 256>>>(W2d, b2d, Wnb);
    dim3 grid(CHUNKS, Bv);
    main_kernel<<<grid, 256>>>(loc, deadline, W3d, b3d, bnb, out);
    tail_kernel<<<Bv, Dv>>>(depot, Wdep, bdep, out);
}

// round 3
// speedup vs baseline: 1.8003x; 1.5293x over previous
#include <cuda_runtime.h>
#include <float.h>

#define Bv 64
#define Nv 1024
#define Dv 128
#define Kv 6
#define CHUNKS 4      // 256 rows per main block

__device__ float  g_ABC[Kv * Dv * 3];              // [k][d][{A,B,C}]
__device__ float  g_partial[Bv * CHUNKS * 2 * Dv]; // per (b, chunk, half) row-sums
__device__ float4 g_sorted[Bv * Nv];               // (x, y, idx_bits, 0) x-sorted

// ---------------------------------------------------------------------------
// Kernel A: fold W2d/b2d through Wnb. One warp per (k,d).
// ---------------------------------------------------------------------------
__global__ __launch_bounds__(256) void abc_kernel(
    const float* __restrict__ W2d, const float* __restrict__ b2d,
    const float* __restrict__ Wnb)
{
    int wid  = blockIdx.x * 8 + (threadIdx.x >> 5);   // 0..767
    int k    = wid >> 7, d = wid & (Dv - 1);
    int lane = threadIdx.x & 31;

    const float4* w4 = (const float4*)(Wnb + (size_t)d * (Kv * Dv) + k * Dv);
    float4 v  = w4[lane];
    const float4* w2 = (const float4*)W2d;
    float4 p0 = w2[lane * 2], p1 = w2[lane * 2 + 1];
    float4 bb = ((const float4*)b2d)[lane];

    float A = fmaf(v.x, p0.x, fmaf(v.y, p0.z, fmaf(v.z, p1.x, v.w * p1.z)));
    float B = fmaf(v.x, p0.y, fmaf(v.y, p0.w, fmaf(v.z, p1.y, v.w * p1.w)));
    float C = fmaf(v.x, bb.x, fmaf(v.y, bb.y, fmaf(v.z, bb.z, v.w * bb.w)));
#pragma unroll
    for (int s = 16; s > 0; s >>= 1) {
        A += __shfl_xor_sync(0xffffffffu, A, s);
        B += __shfl_xor_sync(0xffffffffu, B, s);
        C += __shfl_xor_sync(0xffffffffu, C, s);
    }
    if (lane == 0) {
        int base = (k * Dv + d) * 3;
        g_ABC[base + 0] = A; g_ABC[base + 1] = B; g_ABC[base + 2] = C;
    }
}

// ---------------------------------------------------------------------------
// Kernel S: per-batch bitonic sort of the 1024 points by x (payload: y, idx).
// Sort stability irrelevant: only x-monotonicity is used for pruning.
// ---------------------------------------------------------------------------
__global__ __launch_bounds__(512) void sort_kernel(const float* __restrict__ loc)
{
    __shared__ float kx[Nv];
    __shared__ float ky[Nv];
    __shared__ int   kid[Nv];
    const int b = blockIdx.x, t = threadIdx.x;

    const float2* lb = (const float2*)(loc + (size_t)b * Nv * 2);
    for (int i = t; i < Nv; i += 512) {
        float2 p = lb[i];
        kx[i] = p.x; ky[i] = p.y; kid[i] = i;
    }
    __syncthreads();

    for (int k = 2; k <= Nv; k <<= 1) {
        for (int j = k >> 1; j > 0; j >>= 1) {
            for (int i = t; i < Nv; i += 512) {
                int ixj = i ^ j;
                if (ixj > i) {
                    bool up = ((i & k) == 0);
                    float xa = kx[i], xb = kx[ixj];
                    if (up ? (xa > xb) : (xa < xb)) {
                        kx[i] = xb; kx[ixj] = xa;
                        float ya = ky[i]; ky[i] = ky[ixj]; ky[ixj] = ya;
                        int ia = kid[i]; kid[i] = kid[ixj]; kid[ixj] = ia;
                    }
                }
            }
            __syncthreads();
        }
    }
    for (int i = t; i < Nv; i += 512)
        g_sorted[(size_t)b * Nv + i] =
            make_float4(kx[i], ky[i], __int_as_float(kid[i]), 0.f);
}

// ---------------------------------------------------------------------------
// Kernel B: per (batch b, 256 sorted rows). Thread t owns sorted position p.
//   phase 2: outward x-window scan with exact-rounded dd, branchless top-6.
//   phase 3: fused affine features + leaky_relu, d-coalesced writes by orig row.
// ---------------------------------------------------------------------------
__global__ __launch_bounds__(256) void main_kernel(
    const float* __restrict__ loc, const float* __restrict__ deadline,
    const float* __restrict__ W3d, const float* __restrict__ b3d,
    const float* __restrict__ bnb, float* __restrict__ h_out)
{
    __shared__ float4 sxy[Nv];         // sorted (x, y, idx, 0)      16 KB
    __shared__ float2 sl0[Nv];         // batch-0 coords, orig order  8 KB
    __shared__ float4 srow[256];       // (x, y, deadline, origbits)  4 KB
    __shared__ float2 snb[256 * Kv];   // neighbor batch-0 coords    12 KB
    __shared__ float4 sW3[Dv];         // (w0,w1,w2, base)            2 KB
    __shared__ float2 sAB[Kv * Dv];    // (A_k[d], B_k[d])            6 KB
                                       // total = 48 KB exactly

    const int b = blockIdx.y, chunk = blockIdx.x, t = threadIdx.x;

    {
        const float4* gs = g_sorted + (size_t)b * Nv;
        const float2* l0 = (const float2*)loc;
        for (int i = t; i < Nv; i += 256) { sxy[i] = gs[i]; sl0[i] = l0[i]; }
    }
    if (t < Dv) {
        float sumC = 0.f;
#pragma unroll
        for (int k = 0; k < Kv; k++) {
            int base = (k * Dv + t) * 3;
            sAB[k * Dv + t] = make_float2(g_ABC[base], g_ABC[base + 1]);
            sumC += g_ABC[base + 2];
        }
        sW3[t] = make_float4(W3d[t * 3 + 0], W3d[t * 3 + 1], W3d[t * 3 + 2],
                             b3d[t] + bnb[t] + sumC);
    }
    __syncthreads();

    // ---- phase 2: outward scan from sorted position p ----
    const int p = chunk * 256 + t;
    const float4 me = sxy[p];
    const float mx = me.x, my = me.y;
    const int   orig = __float_as_int(me.z);

    float d0 = 0.f,      d1 = FLT_MAX, d2 = FLT_MAX,
          d3 = FLT_MAX,  d4 = FLT_MAX, d5 = FLT_MAX;   // self: dd = 0
    int   i0 = orig, i1 = 0, i2 = 0, i3 = 0, i4 = 0, i5 = 0;

    // branchless sorted-ascending insert of (dd, cj); strict < keeps earlier
#define INS(dd, cj)  do {                                                    \
        bool c0 = dd < d0, c1 = dd < d1, c2 = dd < d2,                       \
             c3 = dd < d3, c4 = dd < d4, c5 = dd < d5;                       \
        float m0 = fmaxf(d0, dd), m1 = fmaxf(d1, dd), m2 = fmaxf(d2, dd),    \
              m3 = fmaxf(d3, dd), m4 = fmaxf(d4, dd);                        \
        int   w0 = c0 ? i0 : cj, w1 = c1 ? i1 : cj, w2 = c2 ? i2 : cj,       \
              w3 = c3 ? i3 : cj, w4 = c4 ? i4 : cj;                          \
        d5 = c5 ? m4 : d5;  i5 = c5 ? w4 : i5;                               \
        d4 = c4 ? m3 : d4;  i4 = c4 ? w3 : i4;                               \
        d3 = c3 ? m2 : d3;  i3 = c3 ? w2 : i3;                               \
        d2 = c2 ? m1 : d2;  i2 = c2 ? w1 : i2;                               \
        d1 = c1 ? m0 : d1;  i1 = c1 ? w0 : i1;                               \
        d0 = c0 ? dd : d0;  i0 = c0 ? cj : i0;                               \
    } while (0)

    for (int j = p - 1; j >= 0; j--) {                 // left scan
        float4 c = sxy[j];
        float dx  = c.x - mx;
        float dxx = __fmul_rn(dx, dx);
        if (dxx > d5 * 1.000002f) break;               // conservative prune
        float dy  = c.y - my;
        float dd  = __fadd_rn(dxx, __fmul_rn(dy, dy)); // reference rounding
        int   cj  = __float_as_int(c.z);
        INS(dd, cj);
    }
    for (int j = p + 1; j < Nv; j++) {                 // right scan
        float4 c = sxy[j];
        float dx  = c.x - mx;
        float dxx = __fmul_rn(dx, dx);
        if (dxx > d5 * 1.000002f) break;
        float dy  = c.y - my;
        float dd  = __fadd_rn(dxx, __fmul_rn(dy, dy));
        int   cj  = __float_as_int(c.z);
        INS(dd, cj);
    }
#undef INS

    snb[t*Kv+0] = sl0[i0]; snb[t*Kv+1] = sl0[i1]; snb[t*Kv+2] = sl0[i2];
    snb[t*Kv+3] = sl0[i3]; snb[t*Kv+4] = sl0[i4]; snb[t*Kv+5] = sl0[i5];
    srow[t] = make_float4(mx, my, deadline[(size_t)b * Nv + orig], me.z);
    __syncthreads();

    // ---- phase 3: features; thread t = (d = t&127, half = t>>7) ----
    const int d    = t & (Dv - 1);
    const int half = t >> 7;
    const float4 w = sW3[d];
    float A[Kv], Bc[Kv];
#pragma unroll
    for (int k = 0; k < Kv; k++) { float2 ab = sAB[k * Dv + d]; A[k] = ab.x; Bc[k] = ab.y; }

    float acc = 0.f;
#pragma unroll 2
    for (int r = 0; r < 128; r++) {
        int rr = half * 128 + r;
        float4 rd = srow[rr];                       // broadcast LDS.128
        float v = w.w;
        v = fmaf(rd.x, w.x, v);
        v = fmaf(rd.y, w.y, v);
        v = fmaf(rd.z, w.z, v);
#pragma unroll
        for (int k = 0; k < Kv; k++) {
            float2 nb = snb[rr * Kv + k];           // broadcast LDS.64
            v = fmaf(nb.x, A[k], v);
            v = fmaf(nb.y, Bc[k], v);
        }
        v = fmaxf(v, 0.01f * v);                    // leaky_relu(0.01)
        int orow = __float_as_int(rd.w);
        h_out[((size_t)b * 1025 + 1 + orow) * Dv + d] = v;  // coalesced in d
        acc += v;
    }
    g_partial[(((size_t)b * CHUNKS + chunk) * 2 + half) * Dv + d] = acc;
}

// ---------------------------------------------------------------------------
// Kernel C: depot row + mean over axis 1 (1025 rows)
// ---------------------------------------------------------------------------
__global__ void tail_kernel(const float* __restrict__ depot,
                            const float* __restrict__ Wdep,
                            const float* __restrict__ bdep,
                            float* __restrict__ out)
{
    int b = blockIdx.x, d = threadIdx.x;
    float v = bdep[d];
    v = fmaf(depot[b * 2 + 0], Wdep[d * 2 + 0], v);
    v = fmaf(depot[b * 2 + 1], Wdep[d * 2 + 1], v);
    v = fmaxf(v, 0.01f * v);
    out[(size_t)b * 1025 * Dv + d] = v;             // h[b, 0, d]
    float s = v;
#pragma unroll
    for (int c = 0; c < CHUNKS * 2; c++)
        s += g_partial[((size_t)b * CHUNKS * 2 + c) * Dv + d];
    out[(size_t)Bv * 1025 * Dv + b * Dv + d] = s / 1025.0f;
}

// ---------------------------------------------------------------------------
extern "C" void kernel_launch(void* const* d_in, const int* in_sizes, int n_in,
                              void* d_out, int out_size)
{
    const float* loc      = (const float*)d_in[0];
    const float* deadline = (const float*)d_in[1];
    const float* depot    = (const float*)d_in[2];
    const float* W3d      = (const float*)d_in[3];
    const float* b3d      = (const float*)d_in[4];
    const float* W2d      = (const float*)d_in[5];
    const float* b2d      = (const float*)d_in[6];
    const float* Wnb      = (const float*)d_in[7];
    const float* bnb      = (const float*)d_in[8];
    const float* Wdep     = (const float*)d_in[9];
    const float* bdep     = (const float*)d_in[10];
    float* out = (float*)d_out;

    abc_kernel<<<96, 256>>>(W2d, b2d, Wnb);
    sort_kernel<<<Bv, 512>>>(loc);
    dim3 grid(CHUNKS, Bv);
    main_kernel<<<grid, 256>>>(loc, deadline, W3d, b3d, bnb, out);
    tail_kernel<<<Bv, Dv>>>(depot, Wdep, bdep, out);
}